// round 1
// baseline (speedup 1.0000x reference)
#include <cuda_runtime.h>

#define BQ 16384
#define EE 8
#define CC 1000
#define DD 59
#define H1N 256
#define H2N 128
#define EPSF 1e-8f
#define LN_EPSF 1e-5f
#define ROWS 16

__device__ __forceinline__ float wsum(float v) {
    #pragma unroll
    for (int o = 16; o; o >>= 1) v += __shfl_xor_sync(0xffffffffu, v, o);
    return v;
}

// ---------------------------------------------------------------------------
// Kernel 1: feature extraction. One block per batch row, 256 threads.
// Warp e handles expert e. Full 8x1000 tile staged in smem.
// ---------------------------------------------------------------------------
__global__ __launch_bounds__(256) void feat_kernel(
    const float* __restrict__ post, float* __restrict__ feats_out)
{
    __shared__ float sp[EE * CC];     // 32 KB
    __shared__ float smp[CC];         // class mean over experts
    __shared__ float slmp[CC];        // log(mean + eps)
    __shared__ float red[24];         // 8 warps x {ment, mn2, cv}
    __shared__ float wa[EE][7];       // per-expert: ent,topk,maxp,gap,dot,pn,kl
    __shared__ float sfeat[DD];
    __shared__ float s_mn;

    const int tid  = threadIdx.x;
    const int row  = blockIdx.x;
    const int w    = tid >> 5;
    const int lane = tid & 31;

    // ---- load 8000 floats (float4, coalesced) ----
    {
        const float4* src = reinterpret_cast<const float4*>(post + (size_t)row * (EE * CC));
        float4* dst = reinterpret_cast<float4*>(sp);
        #pragma unroll 2
        for (int i = tid; i < (EE * CC) / 4; i += 256) dst[i] = src[i];
    }
    __syncthreads();

    // ---- per-class mean, log-mean; partials for mean_ent, ||mp||^2, class var ----
    {
        float ment = 0.f, mn2 = 0.f, cv = 0.f;
        for (int c = tid; c < CC; c += 256) {
            float s = 0.f;
            #pragma unroll
            for (int e = 0; e < EE; e++) s += sp[e * CC + c];
            float mp = s * (1.0f / EE);
            smp[c] = mp;
            float lmp = __logf(mp + EPSF);
            slmp[c] = lmp;
            ment = fmaf(mp, lmp, ment);
            mn2  = fmaf(mp, mp, mn2);
            #pragma unroll
            for (int e = 0; e < EE; e++) {
                float d = sp[e * CC + c] - mp;
                cv = fmaf(d, d, cv);
            }
        }
        ment = wsum(ment); mn2 = wsum(mn2); cv = wsum(cv);
        if (lane == 0) { red[w * 3 + 0] = ment; red[w * 3 + 1] = mn2; red[w * 3 + 2] = cv; }
    }
    __syncthreads();

    // ---- per-expert stats (warp w == expert w) ----
    {
        const float* pe = sp + w * CC;
        float ent = 0.f, sq = 0.f, dot = 0.f, kl = 0.f;
        float t0 = -1e30f, t1 = -1e30f, t2 = -1e30f, t3 = -1e30f, t4 = -1e30f;
        for (int c = lane; c < CC; c += 32) {
            float p  = pe[c];
            float lp = __logf(p + EPSF);
            ent = fmaf(p, lp, ent);
            sq  = fmaf(p, p, sq);
            dot = fmaf(p, smp[c], dot);
            kl  = fmaf(p, lp - slmp[c], kl);
            if (p > t4) {                       // rarely taken
                if      (p > t0) { t4 = t3; t3 = t2; t2 = t1; t1 = t0; t0 = p; }
                else if (p > t1) { t4 = t3; t3 = t2; t2 = t1; t1 = p; }
                else if (p > t2) { t4 = t3; t3 = t2; t2 = p; }
                else if (p > t3) { t4 = t3; t3 = p; }
                else             { t4 = p; }
            }
        }
        ent = wsum(ent); sq = wsum(sq); dot = wsum(dot); kl = wsum(kl);

        // warp top-5 merge: pop head of each lane's sorted list, 5 rounds
        float top[5];
        int ptr = 0;
        #pragma unroll
        for (int k = 0; k < 5; k++) {
            float v = t0;
            if      (ptr == 1) v = t1;
            else if (ptr == 2) v = t2;
            else if (ptr == 3) v = t3;
            else if (ptr == 4) v = t4;
            else if (ptr >= 5) v = -1e30f;
            float m = v;
            #pragma unroll
            for (int o = 16; o; o >>= 1) m = fmaxf(m, __shfl_xor_sync(0xffffffffu, m, o));
            top[k] = m;
            unsigned msk = __ballot_sync(0xffffffffu, v == m);
            if (lane == (__ffs(msk) - 1)) ptr++;
        }

        if (lane == 0) {
            float tkm = top[0] + top[1] + top[2] + top[3] + top[4];
            wa[w][0] = -ent;
            wa[w][1] = tkm;
            wa[w][2] = top[0];
            wa[w][3] = top[0] - top[1];
            wa[w][4] = dot;
            wa[w][5] = fmaxf(sqrtf(sq), EPSF);
            wa[w][6] = kl;
        }
    }
    __syncthreads();

    // ---- globals (thread 0) ----
    if (tid == 0) {
        float ment = 0.f, mn2 = 0.f, cv = 0.f;
        #pragma unroll
        for (int i = 0; i < 8; i++) { ment += red[i*3]; mn2 += red[i*3+1]; cv += red[i*3+2]; }
        s_mn = fmaxf(sqrtf(mn2), EPSF);
        sfeat[56] = -ment;
        sfeat[57] = cv * (1.0f / (7.0f * (float)CC));
        float mm = 0.f;
        #pragma unroll
        for (int e = 0; e < EE; e++) mm += wa[e][2];
        mm *= (1.0f / EE);
        float sv = 0.f;
        #pragma unroll
        for (int e = 0; e < EE; e++) { float d = wa[e][2] - mm; sv = fmaf(d, d, sv); }
        sfeat[58] = sqrtf(sv / 7.0f);
    }
    __syncthreads();

    if (tid < EE) {
        int e = tid;
        sfeat[e]        = wa[e][0];
        sfeat[8 + e]    = wa[e][1];
        sfeat[16 + e]   = 1.0f - wa[e][1];
        sfeat[24 + e]   = wa[e][2];
        sfeat[32 + e]   = wa[e][3];
        sfeat[40 + e]   = wa[e][4] / (wa[e][5] * s_mn);
        sfeat[48 + e]   = wa[e][6];
    }
    __syncthreads();

    if (tid < DD) {
        float v = sfeat[tid];
        v = fminf(fmaxf(v, -100.0f), 100.0f);
        feats_out[(size_t)row * DD + tid] = v;
    }
}

// ---------------------------------------------------------------------------
// Kernel 2: MLP. 16 rows per block, 256 threads.
// ---------------------------------------------------------------------------
__global__ __launch_bounds__(256) void mlp_kernel(
    const float* __restrict__ feats,
    const float* __restrict__ W1, const float* __restrict__ b1,
    const float* __restrict__ g1, const float* __restrict__ be1,
    const float* __restrict__ W2, const float* __restrict__ b2,
    const float* __restrict__ g2, const float* __restrict__ be2,
    const float* __restrict__ W3, const float* __restrict__ b3,
    float* __restrict__ wout, float* __restrict__ lout)
{
    __shared__ float sf[ROWS][60];
    __shared__ float sh1[ROWS][H1N];
    __shared__ float sh2[ROWS][H2N];
    __shared__ float spart[ROWS][H2N];
    __shared__ float smu[ROWS], srs[ROWS];

    const int tid = threadIdx.x;
    const int rb  = blockIdx.x * ROWS;
    const int w   = tid >> 5;
    const int lane = tid & 31;

    // load feats (contiguous region)
    for (int i = tid; i < ROWS * DD; i += 256)
        sf[i / DD][i % DD] = feats[(size_t)rb * DD + i];
    __syncthreads();

    // ---- layer 1: thread j = neuron, 16 row-accumulators ----
    {
        const int j = tid;
        float acc[ROWS];
        #pragma unroll
        for (int r = 0; r < ROWS; r++) acc[r] = 0.f;
        for (int d = 0; d < DD; d++) {
            float ww = W1[d * H1N + j];
            #pragma unroll
            for (int r = 0; r < ROWS; r++) acc[r] = fmaf(sf[r][d], ww, acc[r]);
        }
        float bb = b1[j];
        #pragma unroll
        for (int r = 0; r < ROWS; r++) sh1[r][j] = acc[r] + bb;
    }
    __syncthreads();

    // LN1 stats: warp handles 2 rows
    #pragma unroll
    for (int rr = 0; rr < 2; rr++) {
        int r = w * 2 + rr;
        float s = 0.f, s2 = 0.f;
        for (int j = lane; j < H1N; j += 32) { float v = sh1[r][j]; s += v; s2 = fmaf(v, v, s2); }
        s = wsum(s); s2 = wsum(s2);
        if (lane == 0) {
            float mu = s * (1.0f / H1N);
            smu[r] = mu;
            srs[r] = rsqrtf(s2 * (1.0f / H1N) - mu * mu + LN_EPSF);
        }
    }
    __syncthreads();
    {
        const int j = tid;
        float gg = g1[j], bb = be1[j];
        #pragma unroll
        for (int r = 0; r < ROWS; r++) {
            float v = (sh1[r][j] - smu[r]) * srs[r] * gg + bb;
            sh1[r][j] = fmaxf(v, 0.f);
        }
    }
    __syncthreads();

    // ---- layer 2: split-K across thread halves ----
    {
        const int j    = tid & (H2N - 1);
        const int half = tid >> 7;
        float acc[ROWS];
        #pragma unroll
        for (int r = 0; r < ROWS; r++) acc[r] = 0.f;
        const int k0 = half * 128;
        for (int kk = 0; kk < 128; kk++) {
            int k = k0 + kk;
            float ww = W2[k * H2N + j];
            #pragma unroll
            for (int r = 0; r < ROWS; r++) acc[r] = fmaf(sh1[r][k], ww, acc[r]);
        }
        if (half) {
            #pragma unroll
            for (int r = 0; r < ROWS; r++) spart[r][j] = acc[r];
        }
        __syncthreads();
        if (!half) {
            float bb = b2[j];
            #pragma unroll
            for (int r = 0; r < ROWS; r++) sh2[r][j] = acc[r] + spart[r][j] + bb;
        }
    }
    __syncthreads();

    // LN2 stats
    #pragma unroll
    for (int rr = 0; rr < 2; rr++) {
        int r = w * 2 + rr;
        float s = 0.f, s2 = 0.f;
        for (int j = lane; j < H2N; j += 32) { float v = sh2[r][j]; s += v; s2 = fmaf(v, v, s2); }
        s = wsum(s); s2 = wsum(s2);
        if (lane == 0) {
            float mu = s * (1.0f / H2N);
            smu[r] = mu;
            srs[r] = rsqrtf(s2 * (1.0f / H2N) - mu * mu + LN_EPSF);
        }
    }
    __syncthreads();
    if (tid < H2N) {
        float gg = g2[tid], bb = be2[tid];
        #pragma unroll
        for (int r = 0; r < ROWS; r++) {
            float v = (sh2[r][tid] - smu[r]) * srs[r] * gg + bb;
            sh2[r][tid] = fmaxf(v, 0.f);
        }
    }
    __syncthreads();

    // ---- layer 3 + outputs ----
    if (tid < ROWS * EE) {
        int r = tid >> 3, e = tid & 7;
        float acc = b3[e];
        for (int k = 0; k < H2N; k++) acc = fmaf(sh2[r][k], W3[k * EE + e], acc);
        lout[(size_t)(rb + r) * EE + e] = acc;
        sf[r][e] = acc;  // reuse sf as logits staging
    }
    __syncthreads();
    if (tid < ROWS) {
        int r = tid;
        float mx = -1e30f;
        #pragma unroll
        for (int e = 0; e < EE; e++) mx = fmaxf(mx, sf[r][e]);
        float ex[EE]; float s = 0.f;
        #pragma unroll
        for (int e = 0; e < EE; e++) { ex[e] = __expf(sf[r][e] - mx); s += ex[e]; }
        float inv = 1.0f / s;
        #pragma unroll
        for (int e = 0; e < EE; e++) wout[(size_t)(rb + r) * EE + e] = ex[e] * inv;
    }
}

extern "C" void kernel_launch(void* const* d_in, const int* in_sizes, int n_in,
                              void* d_out, int out_size)
{
    const float* post = (const float*)d_in[0];
    const float* W1   = (const float*)d_in[1];
    const float* b1   = (const float*)d_in[2];
    const float* g1   = (const float*)d_in[3];
    const float* be1  = (const float*)d_in[4];
    const float* W2   = (const float*)d_in[5];
    const float* b2   = (const float*)d_in[6];
    const float* g2   = (const float*)d_in[7];
    const float* be2  = (const float*)d_in[8];
    const float* W3   = (const float*)d_in[9];
    const float* b3   = (const float*)d_in[10];

    float* out  = (float*)d_out;
    float* wout = out;                         // weights  (B, 8)
    float* lout = out + (size_t)BQ * EE;       // logits   (B, 8)
    float* fout = out + (size_t)BQ * EE * 2;   // feats    (B, 59)

    feat_kernel<<<BQ, 256>>>(post, fout);
    mlp_kernel<<<BQ / ROWS, 256>>>(fout, W1, b1, g1, be1, W2, b2, g2, be2, W3, b3,
                                   wout, lout);
}

// round 2
// speedup vs baseline: 1.2300x; 1.2300x over previous
#include <cuda_runtime.h>

#define BQ 16384
#define EE 8
#define CC 1000
#define DD 59
#define H1N 256
#define H2N 128
#define EPSF 1e-8f
#define LN_EPSF 1e-5f
#define ROWS 16
#define LN2F 0.69314718055994530942f

__device__ __forceinline__ float wsum(float v) {
    #pragma unroll
    for (int o = 16; o; o >>= 1) v += __shfl_xor_sync(0xffffffffu, v, o);
    return v;
}

// branch-free insert into sorted-descending 5-register list (9 FMNMX)
__device__ __forceinline__ void ins5(float& a0, float& a1, float& a2, float& a3,
                                     float& a4, float v) {
    float h;
    h = fmaxf(a0, v); v = fminf(a0, v); a0 = h;
    h = fmaxf(a1, v); v = fminf(a1, v); a1 = h;
    h = fmaxf(a2, v); v = fminf(a2, v); a2 = h;
    h = fmaxf(a3, v); v = fminf(a3, v); a3 = h;
    a4 = fmaxf(a4, v);
}

// ---------------------------------------------------------------------------
// Kernel 1: feature extraction. One block per batch row, 512 threads.
// 16 warps: warp w -> expert (w&7), half (w>>3). Branch-free top-5.
// ---------------------------------------------------------------------------
__global__ __launch_bounds__(512, 3) void feat_kernel(
    const float* __restrict__ post, float* __restrict__ feats_out)
{
    __shared__ __align__(16) float sp[EE * CC];     // 32 KB
    __shared__ __align__(8)  float smp[CC];         // class mean
    __shared__ __align__(8)  float slmp2[CC];       // log2(mean + eps)
    __shared__ float redA[16][2];                   // per-warp {ment2, mn2}
    __shared__ float wq[16][4];                     // per-warp {A,B,SQ,DOT}
    __shared__ float wtop[16][5];
    __shared__ float sfeat[DD];

    const int tid  = threadIdx.x;
    const int row  = blockIdx.x;
    const int w    = tid >> 5;
    const int lane = tid & 31;

    // ---- load 8000 floats (float4, coalesced) ----
    {
        const float4* src = reinterpret_cast<const float4*>(post + (size_t)row * (EE * CC));
        float4* dst = reinterpret_cast<float4*>(sp);
        #pragma unroll
        for (int i = 0; i < 4; i++) {
            int idx = tid + i * 512;
            if (idx < (EE * CC) / 4) dst[idx] = src[idx];
        }
    }
    __syncthreads();

    // ---- phase A1: class means, log2-means, global partials ----
    {
        float ment2 = 0.f, mn2 = 0.f;
        for (int c = tid; c < CC; c += 512) {
            float s = sp[c];
            #pragma unroll
            for (int e = 1; e < EE; e++) s += sp[e * CC + c];
            float mp = s * 0.125f;
            smp[c] = mp;
            float l2 = __log2f(mp + EPSF);
            slmp2[c] = l2;
            ment2 = fmaf(mp, l2, ment2);
            mn2   = fmaf(mp, mp, mn2);
        }
        ment2 = wsum(ment2); mn2 = wsum(mn2);
        if (lane == 0) { redA[w][0] = ment2; redA[w][1] = mn2; }
    }
    __syncthreads();

    // ---- phase A2: per-expert sums + branch-free top-5 (float2 pairs) ----
    {
        const int e    = w & 7;
        const int half = w >> 3;
        const float2* p2  = reinterpret_cast<const float2*>(sp + e * CC);
        const float2* m2  = reinterpret_cast<const float2*>(smp);
        const float2* lm2 = reinterpret_cast<const float2*>(slmp2);

        float A = 0.f, B = 0.f, SQ = 0.f, DOT = 0.f;
        float ta0=-1.f, ta1=-1.f, ta2=-1.f, ta3=-1.f, ta4=-1.f;
        float tb0=-1.f, tb1=-1.f, tb2=-1.f, tb3=-1.f, tb4=-1.f;

        const int start = half * 250;
        const int end   = start + 250;
        for (int i = start + lane; i < end; i += 32) {
            float2 pp = p2[i];
            float2 mm = m2[i];
            float2 lm = lm2[i];
            float lx = __log2f(pp.x + EPSF);
            float ly = __log2f(pp.y + EPSF);
            A  = fmaf(pp.x, lx,   A);  A  = fmaf(pp.y, ly,   A);
            B  = fmaf(pp.x, lm.x, B);  B  = fmaf(pp.y, lm.y, B);
            SQ = fmaf(pp.x, pp.x, SQ); SQ = fmaf(pp.y, pp.y, SQ);
            DOT= fmaf(pp.x, mm.x, DOT);DOT= fmaf(pp.y, mm.y, DOT);
            // two independent compare-exchange chains (ILP)
            {
                float c = pp.x, h;
                h = fmaxf(ta0, c); c = fminf(ta0, c); ta0 = h;
                h = fmaxf(ta1, c); c = fminf(ta1, c); ta1 = h;
                h = fmaxf(ta2, c); c = fminf(ta2, c); ta2 = h;
                h = fmaxf(ta3, c); c = fminf(ta3, c); ta3 = h;
                ta4 = fmaxf(ta4, c);
            }
            {
                float d = pp.y, g;
                g = fmaxf(tb0, d); d = fminf(tb0, d); tb0 = g;
                g = fmaxf(tb1, d); d = fminf(tb1, d); tb1 = g;
                g = fmaxf(tb2, d); d = fminf(tb2, d); tb2 = g;
                g = fmaxf(tb3, d); d = fminf(tb3, d); tb3 = g;
                tb4 = fmaxf(tb4, d);
            }
        }
        // merge list b into list a
        ins5(ta0, ta1, ta2, ta3, ta4, tb0);
        ins5(ta0, ta1, ta2, ta3, ta4, tb1);
        ins5(ta0, ta1, ta2, ta3, ta4, tb2);
        ins5(ta0, ta1, ta2, ta3, ta4, tb3);
        ins5(ta0, ta1, ta2, ta3, ta4, tb4);

        A = wsum(A); B = wsum(B); SQ = wsum(SQ); DOT = wsum(DOT);

        // warp top-5 pop-merge (5 rounds)
        float top[5];
        int ptr = 0;
        #pragma unroll
        for (int k = 0; k < 5; k++) {
            float v = ta0;
            if      (ptr == 1) v = ta1;
            else if (ptr == 2) v = ta2;
            else if (ptr == 3) v = ta3;
            else if (ptr == 4) v = ta4;
            else if (ptr >= 5) v = -2.f;
            float m = v;
            #pragma unroll
            for (int o = 16; o; o >>= 1) m = fmaxf(m, __shfl_xor_sync(0xffffffffu, m, o));
            top[k] = m;
            unsigned msk = __ballot_sync(0xffffffffu, v == m);
            if (lane == (__ffs(msk) - 1)) ptr++;
        }

        if (lane == 0) {
            wq[w][0] = A; wq[w][1] = B; wq[w][2] = SQ; wq[w][3] = DOT;
            wtop[w][0] = top[0]; wtop[w][1] = top[1]; wtop[w][2] = top[2];
            wtop[w][3] = top[3]; wtop[w][4] = top[4];
        }
    }
    __syncthreads();

    // ---- per-expert finalize ----
    if (tid < EE) {
        int e = tid;
        float A   = wq[e][0] + wq[e + 8][0];
        float B   = wq[e][1] + wq[e + 8][1];
        float SQ  = wq[e][2] + wq[e + 8][2];
        float DOT = wq[e][3] + wq[e + 8][3];
        float t0 = wtop[e][0], t1 = wtop[e][1], t2 = wtop[e][2],
              t3 = wtop[e][3], t4 = wtop[e][4];
        ins5(t0, t1, t2, t3, t4, wtop[e + 8][0]);
        ins5(t0, t1, t2, t3, t4, wtop[e + 8][1]);
        ins5(t0, t1, t2, t3, t4, wtop[e + 8][2]);
        ins5(t0, t1, t2, t3, t4, wtop[e + 8][3]);
        ins5(t0, t1, t2, t3, t4, wtop[e + 8][4]);

        float mn2T = 0.f;
        #pragma unroll
        for (int i = 0; i < 16; i++) mn2T += redA[i][1];
        float mn = fmaxf(sqrtf(mn2T), EPSF);
        float pn = fmaxf(sqrtf(SQ), EPSF);
        float tkm = t0 + t1 + t2 + t3 + t4;

        sfeat[e]      = -LN2F * A;
        sfeat[8 + e]  = tkm;
        sfeat[16 + e] = 1.0f - tkm;
        sfeat[24 + e] = t0;
        sfeat[32 + e] = t0 - t1;
        sfeat[40 + e] = DOT / (pn * mn);
        sfeat[48 + e] = LN2F * (A - B);
    }
    __syncthreads();

    // ---- globals ----
    if (tid == 0) {
        float ment2T = 0.f, mn2T = 0.f, SQall = 0.f;
        #pragma unroll
        for (int i = 0; i < 16; i++) {
            ment2T += redA[i][0];
            mn2T   += redA[i][1];
            SQall  += wq[i][2];
        }
        sfeat[56] = -LN2F * ment2T;
        sfeat[57] = (SQall - 8.0f * mn2T) * (1.0f / 7000.0f);
        float mm = 0.f;
        #pragma unroll
        for (int e = 0; e < EE; e++) mm += sfeat[24 + e];
        mm *= 0.125f;
        float sv = 0.f;
        #pragma unroll
        for (int e = 0; e < EE; e++) { float d = sfeat[24 + e] - mm; sv = fmaf(d, d, sv); }
        sfeat[58] = sqrtf(sv * (1.0f / 7.0f));
    }
    __syncthreads();

    if (tid < DD) {
        float v = sfeat[tid];
        v = fminf(fmaxf(v, -100.0f), 100.0f);
        feats_out[(size_t)row * DD + tid] = v;
    }
}

// ---------------------------------------------------------------------------
// Kernel 2: MLP. 16 rows per block, 256 threads. float4 smem reads.
// ---------------------------------------------------------------------------
__global__ __launch_bounds__(256, 4) void mlp_kernel(
    const float* __restrict__ feats,
    const float* __restrict__ W1, const float* __restrict__ b1,
    const float* __restrict__ g1, const float* __restrict__ be1,
    const float* __restrict__ W2, const float* __restrict__ b2,
    const float* __restrict__ g2, const float* __restrict__ be2,
    const float* __restrict__ W3, const float* __restrict__ b3,
    float* __restrict__ wout, float* __restrict__ lout)
{
    __shared__ __align__(16) float sf[ROWS][60];     // 240B stride, 16B-divisible
    __shared__ __align__(16) float sh1[ROWS][H1N];
    __shared__ __align__(16) float sh2[ROWS][H2N];
    __shared__ __align__(16) float spart[ROWS][H2N];
    __shared__ __align__(16) float W3t[EE * H2N];    // transposed W3 [e][k]
    __shared__ float smu[ROWS], srs[ROWS];

    const int tid  = threadIdx.x;
    const int rb   = blockIdx.x * ROWS;
    const int w    = tid >> 5;
    const int lane = tid & 31;

    // load feats + transpose W3
    for (int i = tid; i < ROWS * DD; i += 256)
        sf[i / DD][i % DD] = feats[(size_t)rb * DD + i];
    for (int i = tid; i < H2N * EE; i += 256) {
        int k = i >> 3, e = i & 7;
        W3t[e * H2N + k] = W3[i];
    }
    __syncthreads();

    // ---- layer 1: thread j = neuron, float4 over d ----
    {
        const int j = tid;
        float acc[ROWS];
        #pragma unroll
        for (int r = 0; r < ROWS; r++) acc[r] = 0.f;
        for (int d = 0; d < 56; d += 4) {
            float w0 = W1[(d + 0) * H1N + j];
            float w1 = W1[(d + 1) * H1N + j];
            float w2 = W1[(d + 2) * H1N + j];
            float w3 = W1[(d + 3) * H1N + j];
            #pragma unroll
            for (int r = 0; r < ROWS; r++) {
                float4 f = *reinterpret_cast<const float4*>(&sf[r][d]);
                acc[r] = fmaf(f.x, w0, acc[r]);
                acc[r] = fmaf(f.y, w1, acc[r]);
                acc[r] = fmaf(f.z, w2, acc[r]);
                acc[r] = fmaf(f.w, w3, acc[r]);
            }
        }
        #pragma unroll
        for (int d = 56; d < DD; d++) {
            float ww = W1[d * H1N + j];
            #pragma unroll
            for (int r = 0; r < ROWS; r++) acc[r] = fmaf(sf[r][d], ww, acc[r]);
        }
        float bb = b1[j];
        #pragma unroll
        for (int r = 0; r < ROWS; r++) sh1[r][j] = acc[r] + bb;
    }
    __syncthreads();

    // LN1 stats: warp handles 2 rows
    #pragma unroll
    for (int rr = 0; rr < 2; rr++) {
        int r = w * 2 + rr;
        float s = 0.f, s2 = 0.f;
        for (int j = lane; j < H1N; j += 32) { float v = sh1[r][j]; s += v; s2 = fmaf(v, v, s2); }
        s = wsum(s); s2 = wsum(s2);
        if (lane == 0) {
            float mu = s * (1.0f / H1N);
            smu[r] = mu;
            srs[r] = rsqrtf(s2 * (1.0f / H1N) - mu * mu + LN_EPSF);
        }
    }
    __syncthreads();
    {
        const int j = tid;
        float gg = g1[j], bb = be1[j];
        #pragma unroll
        for (int r = 0; r < ROWS; r++) {
            float v = (sh1[r][j] - smu[r]) * srs[r] * gg + bb;
            sh1[r][j] = fmaxf(v, 0.f);
        }
    }
    __syncthreads();

    // ---- layer 2: split-K halves, float4 over k ----
    {
        const int j    = tid & (H2N - 1);
        const int half = tid >> 7;
        float acc[ROWS];
        #pragma unroll
        for (int r = 0; r < ROWS; r++) acc[r] = 0.f;
        const int k0 = half * 128;
        for (int kk = 0; kk < 128; kk += 4) {
            int k = k0 + kk;
            float w0 = W2[(k + 0) * H2N + j];
            float w1 = W2[(k + 1) * H2N + j];
            float w2 = W2[(k + 2) * H2N + j];
            float w3 = W2[(k + 3) * H2N + j];
            #pragma unroll
            for (int r = 0; r < ROWS; r++) {
                float4 h = *reinterpret_cast<const float4*>(&sh1[r][k]);
                acc[r] = fmaf(h.x, w0, acc[r]);
                acc[r] = fmaf(h.y, w1, acc[r]);
                acc[r] = fmaf(h.z, w2, acc[r]);
                acc[r] = fmaf(h.w, w3, acc[r]);
            }
        }
        if (half) {
            #pragma unroll
            for (int r = 0; r < ROWS; r++) spart[r][j] = acc[r];
        }
        __syncthreads();
        if (!half) {
            float bb = b2[j];
            #pragma unroll
            for (int r = 0; r < ROWS; r++) sh2[r][j] = acc[r] + spart[r][j] + bb;
        }
    }
    __syncthreads();

    // LN2 stats
    #pragma unroll
    for (int rr = 0; rr < 2; rr++) {
        int r = w * 2 + rr;
        float s = 0.f, s2 = 0.f;
        for (int j = lane; j < H2N; j += 32) { float v = sh2[r][j]; s += v; s2 = fmaf(v, v, s2); }
        s = wsum(s); s2 = wsum(s2);
        if (lane == 0) {
            float mu = s * (1.0f / H2N);
            smu[r] = mu;
            srs[r] = rsqrtf(s2 * (1.0f / H2N) - mu * mu + LN_EPSF);
        }
    }
    __syncthreads();
    if (tid < H2N) {
        float gg = g2[tid], bb = be2[tid];
        #pragma unroll
        for (int r = 0; r < ROWS; r++) {
            float v = (sh2[r][tid] - smu[r]) * srs[r] * gg + bb;
            sh2[r][tid] = fmaxf(v, 0.f);
        }
    }
    __syncthreads();

    // ---- layer 3 (vectorized via transposed W3) + outputs ----
    if (tid < ROWS * EE) {
        int r = tid >> 3, e = tid & 7;
        float acc = b3[e];
        for (int k = 0; k < H2N; k += 4) {
            float4 h = *reinterpret_cast<const float4*>(&sh2[r][k]);
            float4 ww = *reinterpret_cast<const float4*>(&W3t[e * H2N + k]);
            acc = fmaf(h.x, ww.x, acc);
            acc = fmaf(h.y, ww.y, acc);
            acc = fmaf(h.z, ww.z, acc);
            acc = fmaf(h.w, ww.w, acc);
        }
        lout[(size_t)(rb + r) * EE + e] = acc;
        sf[r][e] = acc;  // stage logits
    }
    __syncthreads();
    if (tid < ROWS) {
        int r = tid;
        float mx = -1e30f;
        #pragma unroll
        for (int e = 0; e < EE; e++) mx = fmaxf(mx, sf[r][e]);
        float ex[EE]; float s = 0.f;
        #pragma unroll
        for (int e = 0; e < EE; e++) { ex[e] = __expf(sf[r][e] - mx); s += ex[e]; }
        float inv = 1.0f / s;
        #pragma unroll
        for (int e = 0; e < EE; e++) wout[(size_t)(rb + r) * EE + e] = ex[e] * inv;
    }
}

extern "C" void kernel_launch(void* const* d_in, const int* in_sizes, int n_in,
                              void* d_out, int out_size)
{
    const float* post = (const float*)d_in[0];
    const float* W1   = (const float*)d_in[1];
    const float* b1   = (const float*)d_in[2];
    const float* g1   = (const float*)d_in[3];
    const float* be1  = (const float*)d_in[4];
    const float* W2   = (const float*)d_in[5];
    const float* b2   = (const float*)d_in[6];
    const float* g2   = (const float*)d_in[7];
    const float* be2  = (const float*)d_in[8];
    const float* W3   = (const float*)d_in[9];
    const float* b3   = (const float*)d_in[10];

    float* out  = (float*)d_out;
    float* wout = out;                         // weights  (B, 8)
    float* lout = out + (size_t)BQ * EE;       // logits   (B, 8)
    float* fout = out + (size_t)BQ * EE * 2;   // feats    (B, 59)

    feat_kernel<<<BQ, 512>>>(post, fout);
    mlp_kernel<<<BQ / ROWS, 256>>>(fout, W1, b1, g1, be1, W2, b2, g2, be2, W3, b3,
                                   wout, lout);
}

// round 3
// speedup vs baseline: 1.3508x; 1.0982x over previous
#include <cuda_runtime.h>

#define BQ 16384
#define EE 8
#define CC 1000
#define DD 59
#define H1N 256
#define H2N 128
#define EPSF 1e-8f
#define LN_EPSF 1e-5f
#define MROWS 16
#define LN2F 0.69314718055994530942f

typedef unsigned long long u64;

__device__ __forceinline__ float wsum(float v) {
    #pragma unroll
    for (int o = 16; o; o >>= 1) v += __shfl_xor_sync(0xffffffffu, v, o);
    return v;
}

// ---- f32x2 packed helpers (sm_100+) ----
__device__ __forceinline__ u64 pk2(float a, float b) {
    u64 r; asm("mov.b64 %0, {%1, %2};" : "=l"(r) : "f"(a), "f"(b)); return r;
}
__device__ __forceinline__ void upk2(u64 v, float& a, float& b) {
    asm("mov.b64 {%0, %1}, %2;" : "=f"(a), "=f"(b) : "l"(v));
}
__device__ __forceinline__ u64 fma2(u64 a, u64 b, u64 c) {
    u64 d; asm("fma.rn.f32x2 %0, %1, %2, %3;" : "=l"(d) : "l"(a), "l"(b), "l"(c)); return d;
}
__device__ __forceinline__ u64 add2(u64 a, u64 b) {
    u64 d; asm("add.rn.f32x2 %0, %1, %2;" : "=l"(d) : "l"(a), "l"(b)); return d;
}
__device__ __forceinline__ u64 mul2(u64 a, u64 b) {
    u64 d; asm("mul.rn.f32x2 %0, %1, %2;" : "=l"(d) : "l"(a), "l"(b)); return d;
}
__device__ __forceinline__ u64 wsum2(u64 v) {
    #pragma unroll
    for (int o = 16; o; o >>= 1) v = add2(v, __shfl_xor_sync(0xffffffffu, v, o));
    return v;
}

// compare-exchange
#define CE(a, b) { float _h = fmaxf(a, b); b = fminf(a, b); a = _h; }

__device__ __forceinline__ void ins5(float& a0, float& a1, float& a2, float& a3,
                                     float& a4, float v) {
    CE(a0, v); CE(a1, v); CE(a2, v); CE(a3, v); a4 = fmaxf(a4, v);
}

// ---------------------------------------------------------------------------
// Kernel 1: feature extraction. One block per row, 512 threads.
// ---------------------------------------------------------------------------
__global__ __launch_bounds__(512, 3) void feat_kernel(
    const float* __restrict__ post, float* __restrict__ feats_out)
{
    __shared__ __align__(16) float sp[EE * CC];
    __shared__ __align__(16) float smp[CC];
    __shared__ __align__(16) float slmp2[CC];
    __shared__ float redA[16][2];
    __shared__ float wq[16][4];
    __shared__ float wtop[16][5];
    __shared__ float sfeat[DD];

    const int tid  = threadIdx.x;
    const int row  = blockIdx.x;
    const int w    = tid >> 5;
    const int lane = tid & 31;

    {
        const float4* src = reinterpret_cast<const float4*>(post + (size_t)row * (EE * CC));
        float4* dst = reinterpret_cast<float4*>(sp);
        #pragma unroll
        for (int i = 0; i < 4; i++) {
            int idx = tid + i * 512;
            if (idx < (EE * CC) / 4) dst[idx] = src[idx];
        }
    }
    __syncthreads();

    // ---- phase A1: class means, log2-means (float2 per thread) ----
    {
        float ment2 = 0.f, mn2 = 0.f;
        if (tid < 500) {
            const float2* sp2 = reinterpret_cast<const float2*>(sp);
            float2 a = sp2[tid];
            #pragma unroll
            for (int e = 1; e < EE; e++) {
                float2 v = sp2[e * 500 + tid];
                a.x += v.x; a.y += v.y;
            }
            float2 mp; mp.x = a.x * 0.125f; mp.y = a.y * 0.125f;
            float2 lm; lm.x = __log2f(mp.x + EPSF); lm.y = __log2f(mp.y + EPSF);
            reinterpret_cast<float2*>(smp)[tid] = mp;
            reinterpret_cast<float2*>(slmp2)[tid] = lm;
            ment2 = fmaf(mp.x, lm.x, 0.f); ment2 = fmaf(mp.y, lm.y, ment2);
            mn2   = fmaf(mp.x, mp.x, 0.f); mn2   = fmaf(mp.y, mp.y, mn2);
        }
        ment2 = wsum(ment2); mn2 = wsum(mn2);
        if (lane == 0) { redA[w][0] = ment2; redA[w][1] = mn2; }
    }
    __syncthreads();

    // ---- phase A2: per-expert sums + top-5 (float4, sort4 + staircase) ----
    {
        const int e = w & 7;
        const int h = w >> 3;
        const float4* p4 = reinterpret_cast<const float4*>(sp + e * CC);
        const float4* m4 = reinterpret_cast<const float4*>(smp);
        const float4* l4 = reinterpret_cast<const float4*>(slmp2);

        float A = 0.f, B = 0.f, SQ = 0.f, DOT = 0.f;
        float a0 = -1.f, a1 = -1.f, a2 = -1.f, a3 = -1.f, a4 = -1.f;

        const int end = h * 125 + 125;
        for (int i = h * 125 + lane; i < end; i += 32) {
            float4 p  = p4[i];
            float4 mm = m4[i];
            float4 lm = l4[i];
            float lx = __log2f(p.x + EPSF);
            float ly = __log2f(p.y + EPSF);
            float lz = __log2f(p.z + EPSF);
            float lw = __log2f(p.w + EPSF);
            A = fmaf(p.x, lx, A); A = fmaf(p.y, ly, A);
            A = fmaf(p.z, lz, A); A = fmaf(p.w, lw, A);
            B = fmaf(p.x, lm.x, B); B = fmaf(p.y, lm.y, B);
            B = fmaf(p.z, lm.z, B); B = fmaf(p.w, lm.w, B);
            SQ = fmaf(p.x, p.x, SQ); SQ = fmaf(p.y, p.y, SQ);
            SQ = fmaf(p.z, p.z, SQ); SQ = fmaf(p.w, p.w, SQ);
            DOT = fmaf(p.x, mm.x, DOT); DOT = fmaf(p.y, mm.y, DOT);
            DOT = fmaf(p.z, mm.z, DOT); DOT = fmaf(p.w, mm.w, DOT);

            // sort4 descending: v0 >= v1 >= v2 >= v3
            float v0 = p.x, v1 = p.y, v2 = p.z, v3 = p.w;
            CE(v0, v1); CE(v2, v3); CE(v0, v2); CE(v1, v3); CE(v1, v2);
            // staircase insert into sorted-desc a0..a4
            CE(a0, v0); CE(a1, v0); CE(a2, v0); CE(a3, v0); a4 = fmaxf(a4, v0);
            CE(a1, v1); CE(a2, v1); CE(a3, v1); a4 = fmaxf(a4, v1);
            CE(a2, v2); CE(a3, v2); a4 = fmaxf(a4, v2);
            CE(a3, v3); a4 = fmaxf(a4, v3);
        }

        A = wsum(A); B = wsum(B); SQ = wsum(SQ); DOT = wsum(DOT);

        // warp top-5 pop-merge
        float top[5];
        int ptr = 0;
        #pragma unroll
        for (int k = 0; k < 5; k++) {
            float v = a0;
            if      (ptr == 1) v = a1;
            else if (ptr == 2) v = a2;
            else if (ptr == 3) v = a3;
            else if (ptr == 4) v = a4;
            else if (ptr >= 5) v = -2.f;
            float m = v;
            #pragma unroll
            for (int o = 16; o; o >>= 1) m = fmaxf(m, __shfl_xor_sync(0xffffffffu, m, o));
            top[k] = m;
            unsigned msk = __ballot_sync(0xffffffffu, v == m);
            if (lane == (__ffs(msk) - 1)) ptr++;
        }

        if (lane == 0) {
            wq[w][0] = A; wq[w][1] = B; wq[w][2] = SQ; wq[w][3] = DOT;
            wtop[w][0] = top[0]; wtop[w][1] = top[1]; wtop[w][2] = top[2];
            wtop[w][3] = top[3]; wtop[w][4] = top[4];
        }
    }
    __syncthreads();

    if (tid < EE) {
        int e = tid;
        float A   = wq[e][0] + wq[e + 8][0];
        float B   = wq[e][1] + wq[e + 8][1];
        float SQ  = wq[e][2] + wq[e + 8][2];
        float DOT = wq[e][3] + wq[e + 8][3];
        float t0 = wtop[e][0], t1 = wtop[e][1], t2 = wtop[e][2],
              t3 = wtop[e][3], t4 = wtop[e][4];
        ins5(t0, t1, t2, t3, t4, wtop[e + 8][0]);
        ins5(t0, t1, t2, t3, t4, wtop[e + 8][1]);
        ins5(t0, t1, t2, t3, t4, wtop[e + 8][2]);
        ins5(t0, t1, t2, t3, t4, wtop[e + 8][3]);
        ins5(t0, t1, t2, t3, t4, wtop[e + 8][4]);

        float mn2T = 0.f;
        #pragma unroll
        for (int i = 0; i < 16; i++) mn2T += redA[i][1];
        float mn = fmaxf(sqrtf(mn2T), EPSF);
        float pn = fmaxf(sqrtf(SQ), EPSF);
        float tkm = t0 + t1 + t2 + t3 + t4;

        sfeat[e]      = -LN2F * A;
        sfeat[8 + e]  = tkm;
        sfeat[16 + e] = 1.0f - tkm;
        sfeat[24 + e] = t0;
        sfeat[32 + e] = t0 - t1;
        sfeat[40 + e] = DOT / (pn * mn);
        sfeat[48 + e] = LN2F * (A - B);
    }
    __syncthreads();

    if (tid == 0) {
        float ment2T = 0.f, mn2T = 0.f, SQall = 0.f;
        #pragma unroll
        for (int i = 0; i < 16; i++) {
            ment2T += redA[i][0];
            mn2T   += redA[i][1];
            SQall  += wq[i][2];
        }
        sfeat[56] = -LN2F * ment2T;
        sfeat[57] = (SQall - 8.0f * mn2T) * (1.0f / 7000.0f);
        float mm = 0.f;
        #pragma unroll
        for (int e = 0; e < EE; e++) mm += sfeat[24 + e];
        mm *= 0.125f;
        float sv = 0.f;
        #pragma unroll
        for (int e = 0; e < EE; e++) { float d = sfeat[24 + e] - mm; sv = fmaf(d, d, sv); }
        sfeat[58] = sqrtf(sv * (1.0f / 7.0f));
    }
    __syncthreads();

    if (tid < DD) {
        float v = sfeat[tid];
        v = fminf(fmaxf(v, -100.0f), 100.0f);
        feats_out[(size_t)row * DD + tid] = v;
    }
}

// ---------------------------------------------------------------------------
// Kernel 2: MLP with packed f32x2 FMA, transposed activations.
// 16 rows/block (8 row-pairs), 256 threads.
// smem float layout:
//   sh1t: [256 neurons][20 floats] (8 row-pairs used, pad to 10 u64)  = 5120 f
//   sh2t: [128 neurons][20 floats]                                    = 2560 f
//   union: sft [59][16] | spart [128][18] | W3t [8][132]              = 2304 f
//   misc: negmu (16 f) srs (16 f) slog (128 f)                        =  160 f
// ---------------------------------------------------------------------------
__global__ __launch_bounds__(256) void mlp_kernel(
    const float* __restrict__ feats,
    const float* __restrict__ W1, const float* __restrict__ b1,
    const float* __restrict__ g1, const float* __restrict__ be1,
    const float* __restrict__ W2, const float* __restrict__ b2,
    const float* __restrict__ g2, const float* __restrict__ be2,
    const float* __restrict__ W3, const float* __restrict__ b3,
    float* __restrict__ wout, float* __restrict__ lout)
{
    __shared__ __align__(16) float smem[10144];
    float* sh1t  = smem;                 // u64 view: [j*10 + rp]
    float* sh2t  = smem + 5120;          // u64 view: [j*10 + rp]
    float* sft   = smem + 7680;          // [d*16 + r]
    float* spart = smem + 7680;          // u64 view: [j*9 + rp]
    float* W3t   = smem + 7680;          // [e*132 + k]
    u64*   negmu = (u64*)(smem + 9984);  // [8]
    u64*   srs   = (u64*)(smem + 10000); // [8]
    float* slog  = smem + 10016;         // [16][8]

    u64* sh1tU  = (u64*)sh1t;
    u64* sh2tU  = (u64*)sh2t;
    u64* spartU = (u64*)spart;

    const int tid  = threadIdx.x;
    const int rb   = blockIdx.x * MROWS;
    const int w    = tid >> 5;
    const int lane = tid & 31;

    // load feats transposed: sft[d][r]
    for (int i = tid; i < MROWS * DD; i += 256) {
        int r = i / DD, d = i - r * DD;
        sft[d * 16 + r] = feats[(size_t)rb * DD + i];
    }
    __syncthreads();

    // ---- layer 1: thread = neuron j, 8 packed row-pair accumulators ----
    u64 h1[8];
    {
        const int j = tid;
        u64 acc[8];
        #pragma unroll
        for (int rp = 0; rp < 8; rp++) acc[rp] = 0ull;
        for (int d = 0; d < DD; d++) {
            float wv = W1[d * H1N + j];
            u64 wp = pk2(wv, wv);
            const u64* fp = (const u64*)(sft + d * 16);
            #pragma unroll
            for (int rp = 0; rp < 8; rp++) acc[rp] = fma2(fp[rp], wp, acc[rp]);
        }
        float bb = b1[j];
        u64 bp = pk2(bb, bb);
        #pragma unroll
        for (int rp = 0; rp < 8; rp++) {
            h1[rp] = add2(acc[rp], bp);
            sh1tU[j * 10 + rp] = h1[rp];
        }
    }
    __syncthreads();

    // ---- LN1 stats: warp w handles row-pair w ----
    {
        u64 s = 0ull, q = 0ull;
        #pragma unroll
        for (int m = 0; m < 8; m++) {
            u64 v = sh1tU[(lane + 32 * m) * 10 + w];
            s = add2(s, v);
            q = fma2(v, v, q);
        }
        s = wsum2(s); q = wsum2(q);
        if (lane == 0) {
            float sa, sb, qa, qb;
            upk2(s, sa, sb); upk2(q, qa, qb);
            float mua = sa * (1.0f / H1N), mub = sb * (1.0f / H1N);
            float rsa = rsqrtf(qa * (1.0f / H1N) - mua * mua + LN_EPSF);
            float rsb = rsqrtf(qb * (1.0f / H1N) - mub * mub + LN_EPSF);
            negmu[w] = pk2(-mua, -mub);
            srs[w]   = pk2(rsa, rsb);
        }
    }
    __syncthreads();

    // ---- LN1 apply + relu, store back transposed ----
    {
        const int j = tid;
        u64 gp = pk2(g1[j], g1[j]);
        u64 bp = pk2(be1[j], be1[j]);
        #pragma unroll
        for (int rp = 0; rp < 8; rp++) {
            u64 t = add2(h1[rp], negmu[rp]);
            t = mul2(t, srs[rp]);
            t = fma2(t, gp, bp);
            float x, y; upk2(t, x, y);
            sh1tU[j * 10 + rp] = pk2(fmaxf(x, 0.f), fmaxf(y, 0.f));
        }
    }
    __syncthreads();

    // ---- layer 2: split-K halves ----
    const int j2   = tid & (H2N - 1);
    const int half = tid >> 7;
    u64 h2[8];
    {
        u64 acc[8];
        #pragma unroll
        for (int rp = 0; rp < 8; rp++) acc[rp] = 0ull;
        const int k0 = half * 128;
        for (int kk = 0; kk < 128; kk++) {
            int k = k0 + kk;
            float wv = W2[k * H2N + j2];
            u64 wp = pk2(wv, wv);
            const u64* hp = (const u64*)(sh1t + k * 20);
            #pragma unroll
            for (int rp = 0; rp < 8; rp++) acc[rp] = fma2(hp[rp], wp, acc[rp]);
        }
        if (half) {
            #pragma unroll
            for (int rp = 0; rp < 8; rp++) spartU[j2 * 9 + rp] = acc[rp];
        }
        __syncthreads();
        if (!half) {
            float bb = b2[j2];
            u64 bp = pk2(bb, bb);
            #pragma unroll
            for (int rp = 0; rp < 8; rp++) {
                h2[rp] = add2(add2(acc[rp], spartU[j2 * 9 + rp]), bp);
                sh2tU[j2 * 10 + rp] = h2[rp];
            }
        }
    }
    __syncthreads();

    // ---- LN2 stats ----
    {
        u64 s = 0ull, q = 0ull;
        #pragma unroll
        for (int m = 0; m < 4; m++) {
            u64 v = sh2tU[(lane + 32 * m) * 10 + w];
            s = add2(s, v);
            q = fma2(v, v, q);
        }
        s = wsum2(s); q = wsum2(q);
        if (lane == 0) {
            float sa, sb, qa, qb;
            upk2(s, sa, sb); upk2(q, qa, qb);
            float mua = sa * (1.0f / H2N), mub = sb * (1.0f / H2N);
            float rsa = rsqrtf(qa * (1.0f / H2N) - mua * mua + LN_EPSF);
            float rsb = rsqrtf(qb * (1.0f / H2N) - mub * mub + LN_EPSF);
            negmu[w] = pk2(-mua, -mub);
            srs[w]   = pk2(rsa, rsb);
        }
    }
    __syncthreads();

    // ---- LN2 apply (half0) + W3 transpose load (half1) ----
    if (!half) {
        u64 gp = pk2(g2[j2], g2[j2]);
        u64 bp = pk2(be2[j2], be2[j2]);
        #pragma unroll
        for (int rp = 0; rp < 8; rp++) {
            u64 t = add2(h2[rp], negmu[rp]);
            t = mul2(t, srs[rp]);
            t = fma2(t, gp, bp);
            float x, y; upk2(t, x, y);
            sh2tU[j2 * 10 + rp] = pk2(fmaxf(x, 0.f), fmaxf(y, 0.f));
        }
    } else {
        for (int i = j2; i < H2N * EE; i += 128) {
            int k = i >> 3, e = i & 7;
            W3t[e * 132 + k] = W3[i];
        }
    }
    __syncthreads();

    // ---- layer 3 + logits ----
    if (tid < MROWS * EE) {
        int r = tid >> 3, e = tid & 7;
        float acc = b3[e];
        #pragma unroll 4
        for (int k = 0; k < H2N; k++)
            acc = fmaf(sh2t[k * 20 + r], W3t[e * 132 + k], acc);
        lout[(size_t)(rb + r) * EE + e] = acc;
        slog[r * 8 + e] = acc;
    }
    __syncthreads();
    if (tid < MROWS) {
        int r = tid;
        float mx = -1e30f;
        #pragma unroll
        for (int e = 0; e < EE; e++) mx = fmaxf(mx, slog[r * 8 + e]);
        float ex[EE]; float s = 0.f;
        #pragma unroll
        for (int e = 0; e < EE; e++) { ex[e] = __expf(slog[r * 8 + e] - mx); s += ex[e]; }
        float inv = 1.0f / s;
        #pragma unroll
        for (int e = 0; e < EE; e++) wout[(size_t)(rb + r) * EE + e] = ex[e] * inv;
    }
}

extern "C" void kernel_launch(void* const* d_in, const int* in_sizes, int n_in,
                              void* d_out, int out_size)
{
    const float* post = (const float*)d_in[0];
    const float* W1   = (const float*)d_in[1];
    const float* b1   = (const float*)d_in[2];
    const float* g1   = (const float*)d_in[3];
    const float* be1  = (const float*)d_in[4];
    const float* W2   = (const float*)d_in[5];
    const float* b2   = (const float*)d_in[6];
    const float* g2   = (const float*)d_in[7];
    const float* be2  = (const float*)d_in[8];
    const float* W3   = (const float*)d_in[9];
    const float* b3   = (const float*)d_in[10];

    float* out  = (float*)d_out;
    float* wout = out;                         // weights (B, 8)
    float* lout = out + (size_t)BQ * EE;       // logits  (B, 8)
    float* fout = out + (size_t)BQ * EE * 2;   // feats   (B, 59)

    feat_kernel<<<BQ, 512>>>(post, fout);
    mlp_kernel<<<BQ / MROWS, 256>>>(fout, W1, b1, g1, be1, W2, b2, g2, be2, W3, b3,
                                    wout, lout);
}

// round 4
// speedup vs baseline: 1.4866x; 1.1005x over previous
#include <cuda_runtime.h>

#define BQ 16384
#define EE 8
#define CC 1000
#define DD 59
#define H1N 256
#define H2N 128
#define EPSF 1e-8f
#define LN_EPSF 1e-5f
#define MROWS 32
#define LN2F 0.69314718055994530942f

typedef unsigned long long u64;

__device__ __forceinline__ float wsum(float v) {
    #pragma unroll
    for (int o = 16; o; o >>= 1) v += __shfl_xor_sync(0xffffffffu, v, o);
    return v;
}

// ---- f32x2 packed helpers (sm_100+) ----
__device__ __forceinline__ u64 pk2(float a, float b) {
    u64 r; asm("mov.b64 %0, {%1, %2};" : "=l"(r) : "f"(a), "f"(b)); return r;
}
__device__ __forceinline__ void upk2(u64 v, float& a, float& b) {
    asm("mov.b64 {%0, %1}, %2;" : "=f"(a), "=f"(b) : "l"(v));
}
__device__ __forceinline__ u64 fma2(u64 a, u64 b, u64 c) {
    u64 d; asm("fma.rn.f32x2 %0, %1, %2, %3;" : "=l"(d) : "l"(a), "l"(b), "l"(c)); return d;
}
__device__ __forceinline__ u64 add2(u64 a, u64 b) {
    u64 d; asm("add.rn.f32x2 %0, %1, %2;" : "=l"(d) : "l"(a), "l"(b)); return d;
}
__device__ __forceinline__ u64 mul2(u64 a, u64 b) {
    u64 d; asm("mul.rn.f32x2 %0, %1, %2;" : "=l"(d) : "l"(a), "l"(b)); return d;
}
__device__ __forceinline__ u64 wsum2(u64 v) {
    #pragma unroll
    for (int o = 16; o; o >>= 1) v = add2(v, __shfl_xor_sync(0xffffffffu, v, o));
    return v;
}

#define CE(a, b) { float _h = fmaxf(a, b); b = fminf(a, b); a = _h; }

__device__ __forceinline__ void ins5(float& a0, float& a1, float& a2, float& a3,
                                     float& a4, float v) {
    CE(a0, v); CE(a1, v); CE(a2, v); CE(a3, v); a4 = fmaxf(a4, v);
}

// ---------------------------------------------------------------------------
// Kernel 1: feature extraction. One block per row, 512 threads.
// ---------------------------------------------------------------------------
__global__ __launch_bounds__(512, 3) void feat_kernel(
    const float* __restrict__ post, float* __restrict__ feats_out)
{
    __shared__ __align__(16) float sp[EE * CC];
    __shared__ __align__(16) float smp[CC];
    __shared__ __align__(16) float slmp2[CC];
    __shared__ float redA[16][2];
    __shared__ float wq[16][4];
    __shared__ float wtop[16][5];
    __shared__ float sfeat[DD];

    const int tid  = threadIdx.x;
    const int row  = blockIdx.x;
    const int w    = tid >> 5;
    const int lane = tid & 31;

    {
        const float4* src = reinterpret_cast<const float4*>(post + (size_t)row * (EE * CC));
        float4* dst = reinterpret_cast<float4*>(sp);
        #pragma unroll
        for (int i = 0; i < 4; i++) {
            int idx = tid + i * 512;
            if (idx < (EE * CC) / 4) dst[idx] = src[idx];
        }
    }
    __syncthreads();

    // ---- phase A1: class means, log2-means (f32x2 per thread) ----
    {
        float ment2 = 0.f, mn2 = 0.f;
        if (tid < 500) {
            const u64* spU = reinterpret_cast<const u64*>(sp);
            u64 a = spU[tid];
            #pragma unroll
            for (int e = 1; e < EE; e++) a = add2(a, spU[e * 500 + tid]);
            u64 mp2 = mul2(a, pk2(0.125f, 0.125f));
            float mx, my; upk2(mp2, mx, my);
            float lx = __log2f(mx + EPSF), ly = __log2f(my + EPSF);
            reinterpret_cast<u64*>(smp)[tid]   = mp2;
            reinterpret_cast<u64*>(slmp2)[tid] = pk2(lx, ly);
            ment2 = fmaf(mx, lx, 0.f); ment2 = fmaf(my, ly, ment2);
            mn2   = fmaf(mx, mx, 0.f); mn2   = fmaf(my, my, mn2);
        }
        ment2 = wsum(ment2); mn2 = wsum(mn2);
        if (lane == 0) { redA[w][0] = ment2; redA[w][1] = mn2; }
    }
    __syncthreads();

    // ---- phase A2: per-expert sums + top-5 ----
    {
        const int e = w & 7;
        const int h = w >> 3;
        const float4* p4 = reinterpret_cast<const float4*>(sp + e * CC);
        const float4* m4 = reinterpret_cast<const float4*>(smp);
        const float4* l4 = reinterpret_cast<const float4*>(slmp2);

        float A = 0.f;
        u64 SQ2 = 0ull, DOT2 = 0ull, B2 = 0ull;
        float a0 = 0.f, a1 = 0.f, a2 = 0.f, a3 = 0.f, a4 = 0.f;

        const int base = h * 125 + lane;
        #pragma unroll
        for (int it = 0; it < 4; it++) {
            if (it < 3 || lane < 29) {
                int i = base + it * 32;
                float4 p  = p4[i];
                float4 mm = m4[i];
                float4 lm = l4[i];
                u64 pa = pk2(p.x, p.y), pb = pk2(p.z, p.w);
                SQ2  = fma2(pa, pa, SQ2);              SQ2  = fma2(pb, pb, SQ2);
                DOT2 = fma2(pa, pk2(mm.x, mm.y), DOT2); DOT2 = fma2(pb, pk2(mm.z, mm.w), DOT2);
                B2   = fma2(pa, pk2(lm.x, lm.y), B2);   B2   = fma2(pb, pk2(lm.z, lm.w), B2);
                float lx = __log2f(p.x + EPSF);
                float ly = __log2f(p.y + EPSF);
                float lz = __log2f(p.z + EPSF);
                float lw = __log2f(p.w + EPSF);
                A = fmaf(p.x, lx, A); A = fmaf(p.y, ly, A);
                A = fmaf(p.z, lz, A); A = fmaf(p.w, lw, A);

                float v0 = p.x, v1 = p.y, v2 = p.z, v3 = p.w;
                CE(v0, v1); CE(v2, v3); CE(v0, v2); CE(v1, v3); CE(v1, v2);
                CE(a0, v0); CE(a1, v0); CE(a2, v0); CE(a3, v0); a4 = fmaxf(a4, v0);
                CE(a1, v1); CE(a2, v1); CE(a3, v1); a4 = fmaxf(a4, v1);
                CE(a2, v2); CE(a3, v2); a4 = fmaxf(a4, v2);
                CE(a3, v3); a4 = fmaxf(a4, v3);
            }
        }

        float sqa, sqb, da, db, ba, bb;
        upk2(SQ2, sqa, sqb); upk2(DOT2, da, db); upk2(B2, ba, bb);
        float SQ = sqa + sqb, DOT = da + db, B = ba + bb;

        A = wsum(A); B = wsum(B); SQ = wsum(SQ); DOT = wsum(DOT);

        // warp top-5 pop-merge via redux (all values >= 0)
        float top[5];
        int ptr = 0;
        #pragma unroll
        for (int k = 0; k < 5; k++) {
            float v = a0;
            if      (ptr == 1) v = a1;
            else if (ptr == 2) v = a2;
            else if (ptr == 3) v = a3;
            else if (ptr == 4) v = a4;
            else if (ptr >= 5) v = 0.f;
            unsigned uv = __float_as_uint(v);
            unsigned um = __reduce_max_sync(0xffffffffu, uv);
            top[k] = __uint_as_float(um);
            unsigned msk = __ballot_sync(0xffffffffu, uv == um);
            if (lane == (__ffs(msk) - 1)) ptr++;
        }

        if (lane == 0) {
            wq[w][0] = A; wq[w][1] = B; wq[w][2] = SQ; wq[w][3] = DOT;
            wtop[w][0] = top[0]; wtop[w][1] = top[1]; wtop[w][2] = top[2];
            wtop[w][3] = top[3]; wtop[w][4] = top[4];
        }
    }
    __syncthreads();

    if (tid < EE) {
        int e = tid;
        float A   = wq[e][0] + wq[e + 8][0];
        float B   = wq[e][1] + wq[e + 8][1];
        float SQ  = wq[e][2] + wq[e + 8][2];
        float DOT = wq[e][3] + wq[e + 8][3];
        float t0 = wtop[e][0], t1 = wtop[e][1], t2 = wtop[e][2],
              t3 = wtop[e][3], t4 = wtop[e][4];
        ins5(t0, t1, t2, t3, t4, wtop[e + 8][0]);
        ins5(t0, t1, t2, t3, t4, wtop[e + 8][1]);
        ins5(t0, t1, t2, t3, t4, wtop[e + 8][2]);
        ins5(t0, t1, t2, t3, t4, wtop[e + 8][3]);
        ins5(t0, t1, t2, t3, t4, wtop[e + 8][4]);

        float mn2T = 0.f;
        #pragma unroll
        for (int i = 0; i < 16; i++) mn2T += redA[i][1];
        float mn = fmaxf(sqrtf(mn2T), EPSF);
        float pn = fmaxf(sqrtf(SQ), EPSF);
        float tkm = t0 + t1 + t2 + t3 + t4;

        sfeat[e]      = -LN2F * A;
        sfeat[8 + e]  = tkm;
        sfeat[16 + e] = 1.0f - tkm;
        sfeat[24 + e] = t0;
        sfeat[32 + e] = t0 - t1;
        sfeat[40 + e] = DOT / (pn * mn);
        sfeat[48 + e] = LN2F * (A - B);
    }
    __syncthreads();

    if (tid == 0) {
        float ment2T = 0.f, mn2T = 0.f, SQall = 0.f;
        #pragma unroll
        for (int i = 0; i < 16; i++) {
            ment2T += redA[i][0];
            mn2T   += redA[i][1];
            SQall  += wq[i][2];
        }
        sfeat[56] = -LN2F * ment2T;
        sfeat[57] = (SQall - 8.0f * mn2T) * (1.0f / 7000.0f);
        float mm = 0.f;
        #pragma unroll
        for (int e = 0; e < EE; e++) mm += sfeat[24 + e];
        mm *= 0.125f;
        float sv = 0.f;
        #pragma unroll
        for (int e = 0; e < EE; e++) { float d = sfeat[24 + e] - mm; sv = fmaf(d, d, sv); }
        sfeat[58] = sqrtf(sv * (1.0f / 7.0f));
    }
    __syncthreads();

    if (tid < DD) {
        float v = sfeat[tid];
        v = fminf(fmaxf(v, -100.0f), 100.0f);
        feats_out[(size_t)row * DD + tid] = v;
    }
}

// ---------------------------------------------------------------------------
// Kernel 2: MLP v4. 32 rows/block (16 row-pairs), 256 threads,
// 4-neuron x 4-rowpair register tiles, f32x2 FMAs.
// Dynamic smem layout (bytes):
//   sh1t  @0      : 256 * 17 u64 = 34816   [j*17 + rp]
//   sh2t  @34816  : 128 * 17 u64 = 17408   [j*17 + rp]
//   sft   @52224  : 59 * 16 u64  =  7552   [d*16 + rp]  (union W3t: 8*132 f32)
//   negmu @59776  : 16 u64
//   srs   @59904  : 16 u64
//   slog  @60032  : 32*8 f32 = 1024
// total 61056
// ---------------------------------------------------------------------------
#define MLP_SMEM 61056

__global__ __launch_bounds__(256) void mlp_kernel(
    const float* __restrict__ feats,
    const float* __restrict__ W1, const float* __restrict__ b1,
    const float* __restrict__ g1, const float* __restrict__ be1,
    const float* __restrict__ W2, const float* __restrict__ b2,
    const float* __restrict__ g2, const float* __restrict__ be2,
    const float* __restrict__ W3, const float* __restrict__ b3,
    float* __restrict__ wout, float* __restrict__ lout)
{
    extern __shared__ __align__(16) char smraw[];
    u64*   sh1tU = (u64*)(smraw);
    u64*   sh2tU = (u64*)(smraw + 34816);
    float* sh2tF = (float*)(smraw + 34816);
    u64*   sftU  = (u64*)(smraw + 52224);
    float* sftF  = (float*)(smraw + 52224);
    float* W3t   = (float*)(smraw + 52224);
    u64*   negmu = (u64*)(smraw + 59776);
    u64*   srs   = (u64*)(smraw + 59904);
    float* slog  = (float*)(smraw + 60032);

    const int tid  = threadIdx.x;
    const int rb   = blockIdx.x * MROWS;
    const int w    = tid >> 5;
    const int lane = tid & 31;

    // load feats transposed: sftF[d*32 + r]
    for (int i = tid; i < MROWS * DD; i += 256) {
        int r = i / DD, d = i - r * DD;
        sftF[d * 32 + r] = feats[(size_t)rb * DD + i];
    }
    __syncthreads();

    // ---- layer 1: tile (4 neurons x 4 rowpairs) per thread ----
    const int rg = tid & 3;       // rowpair group
    const int ng = tid >> 2;      // neuron group (0..63)
    u64 h1[4][4];
    {
        u64 acc[4][4];
        #pragma unroll
        for (int i = 0; i < 4; i++)
            #pragma unroll
            for (int m = 0; m < 4; m++) acc[i][m] = 0ull;

        for (int d = 0; d < DD; d++) {
            float4 wv = *reinterpret_cast<const float4*>(&W1[d * H1N + ng * 4]);
            u64 w0 = pk2(wv.x, wv.x), w1 = pk2(wv.y, wv.y);
            u64 w2 = pk2(wv.z, wv.z), w3 = pk2(wv.w, wv.w);
            const u64* fp = sftU + d * 16 + rg * 4;
            u64 f0 = fp[0], f1 = fp[1], f2 = fp[2], f3 = fp[3];
            acc[0][0] = fma2(f0, w0, acc[0][0]); acc[0][1] = fma2(f1, w0, acc[0][1]);
            acc[0][2] = fma2(f2, w0, acc[0][2]); acc[0][3] = fma2(f3, w0, acc[0][3]);
            acc[1][0] = fma2(f0, w1, acc[1][0]); acc[1][1] = fma2(f1, w1, acc[1][1]);
            acc[1][2] = fma2(f2, w1, acc[1][2]); acc[1][3] = fma2(f3, w1, acc[1][3]);
            acc[2][0] = fma2(f0, w2, acc[2][0]); acc[2][1] = fma2(f1, w2, acc[2][1]);
            acc[2][2] = fma2(f2, w2, acc[2][2]); acc[2][3] = fma2(f3, w2, acc[2][3]);
            acc[3][0] = fma2(f0, w3, acc[3][0]); acc[3][1] = fma2(f1, w3, acc[3][1]);
            acc[3][2] = fma2(f2, w3, acc[3][2]); acc[3][3] = fma2(f3, w3, acc[3][3]);
        }
        #pragma unroll
        for (int i = 0; i < 4; i++) {
            int j = ng * 4 + i;
            float bb = b1[j];
            u64 bp = pk2(bb, bb);
            #pragma unroll
            for (int m = 0; m < 4; m++) {
                h1[i][m] = add2(acc[i][m], bp);
                sh1tU[j * 17 + rg * 4 + m] = h1[i][m];
            }
        }
    }
    __syncthreads();

    // ---- LN1 stats: warp w handles rowpairs w and w+8 ----
    #pragma unroll
    for (int rr = 0; rr < 2; rr++) {
        int rp = w + rr * 8;
        u64 s = 0ull, q = 0ull;
        #pragma unroll
        for (int m = 0; m < 8; m++) {
            u64 v = sh1tU[(lane + 32 * m) * 17 + rp];
            s = add2(s, v);
            q = fma2(v, v, q);
        }
        s = wsum2(s); q = wsum2(q);
        if (lane == 0) {
            float sa, sb, qa, qb;
            upk2(s, sa, sb); upk2(q, qa, qb);
            float mua = sa * (1.0f / H1N), mub = sb * (1.0f / H1N);
            float rsa = rsqrtf(qa * (1.0f / H1N) - mua * mua + LN_EPSF);
            float rsb = rsqrtf(qb * (1.0f / H1N) - mub * mub + LN_EPSF);
            negmu[rp] = pk2(-mua, -mub);
            srs[rp]   = pk2(rsa, rsb);
        }
    }
    __syncthreads();

    // ---- LN1 apply + relu from registers ----
    {
        #pragma unroll
        for (int i = 0; i < 4; i++) {
            int j = ng * 4 + i;
            u64 gp = pk2(g1[j], g1[j]);
            u64 bp = pk2(be1[j], be1[j]);
            #pragma unroll
            for (int m = 0; m < 4; m++) {
                int rp = rg * 4 + m;
                u64 t = add2(h1[i][m], negmu[rp]);
                t = mul2(t, srs[rp]);
                t = fma2(t, gp, bp);
                float x, y; upk2(t, x, y);
                sh1tU[j * 17 + rp] = pk2(fmaxf(x, 0.f), fmaxf(y, 0.f));
            }
        }
    }
    __syncthreads();

    // ---- layer 2: tile (4 neurons x 4 rowpairs), k split in halves ----
    const int jg   = ng & 31;     // neuron group 0..31 (128 neurons)
    const int half = tid >> 7;
    u64 h2[4][4];
    {
        u64 acc[4][4];
        #pragma unroll
        for (int i = 0; i < 4; i++)
            #pragma unroll
            for (int m = 0; m < 4; m++) acc[i][m] = 0ull;

        const int k0 = half * 128;
        for (int kk = 0; kk < 128; kk++) {
            int k = k0 + kk;
            float4 wv = *reinterpret_cast<const float4*>(&W2[k * H2N + jg * 4]);
            u64 w0 = pk2(wv.x, wv.x), w1 = pk2(wv.y, wv.y);
            u64 w2_ = pk2(wv.z, wv.z), w3 = pk2(wv.w, wv.w);
            const u64* hp = sh1tU + k * 17 + rg * 4;
            u64 f0 = hp[0], f1 = hp[1], f2 = hp[2], f3 = hp[3];
            acc[0][0] = fma2(f0, w0, acc[0][0]); acc[0][1] = fma2(f1, w0, acc[0][1]);
            acc[0][2] = fma2(f2, w0, acc[0][2]); acc[0][3] = fma2(f3, w0, acc[0][3]);
            acc[1][0] = fma2(f0, w1, acc[1][0]); acc[1][1] = fma2(f1, w1, acc[1][1]);
            acc[1][2] = fma2(f2, w1, acc[1][2]); acc[1][3] = fma2(f3, w1, acc[1][3]);
            acc[2][0] = fma2(f0, w2_, acc[2][0]); acc[2][1] = fma2(f1, w2_, acc[2][1]);
            acc[2][2] = fma2(f2, w2_, acc[2][2]); acc[2][3] = fma2(f3, w2_, acc[2][3]);
            acc[3][0] = fma2(f0, w3, acc[3][0]); acc[3][1] = fma2(f1, w3, acc[3][1]);
            acc[3][2] = fma2(f2, w3, acc[3][2]); acc[3][3] = fma2(f3, w3, acc[3][3]);
        }
        if (half) {
            #pragma unroll
            for (int i = 0; i < 4; i++)
                #pragma unroll
                for (int m = 0; m < 4; m++)
                    sh2tU[(jg * 4 + i) * 17 + rg * 4 + m] = acc[i][m];
        }
        __syncthreads();
        if (!half) {
            #pragma unroll
            for (int i = 0; i < 4; i++) {
                int j = jg * 4 + i;
                float bb = b2[j];
                u64 bp = pk2(bb, bb);
                #pragma unroll
                for (int m = 0; m < 4; m++) {
                    int rp = rg * 4 + m;
                    h2[i][m] = add2(add2(acc[i][m], sh2tU[j * 17 + rp]), bp);
                }
            }
            // store raw for stats
            #pragma unroll
            for (int i = 0; i < 4; i++)
                #pragma unroll
                for (int m = 0; m < 4; m++)
                    sh2tU[(jg * 4 + i) * 17 + rg * 4 + m] = h2[i][m];
        }
    }
    __syncthreads();

    // ---- LN2 stats ----
    #pragma unroll
    for (int rr = 0; rr < 2; rr++) {
        int rp = w + rr * 8;
        u64 s = 0ull, q = 0ull;
        #pragma unroll
        for (int m = 0; m < 4; m++) {
            u64 v = sh2tU[(lane + 32 * m) * 17 + rp];
            s = add2(s, v);
            q = fma2(v, v, q);
        }
        s = wsum2(s); q = wsum2(q);
        if (lane == 0) {
            float sa, sb, qa, qb;
            upk2(s, sa, sb); upk2(q, qa, qb);
            float mua = sa * (1.0f / H2N), mub = sb * (1.0f / H2N);
            float rsa = rsqrtf(qa * (1.0f / H2N) - mua * mua + LN_EPSF);
            float rsb = rsqrtf(qb * (1.0f / H2N) - mub * mub + LN_EPSF);
            negmu[rp] = pk2(-mua, -mub);
            srs[rp]   = pk2(rsa, rsb);
        }
    }
    __syncthreads();

    // ---- LN2 apply (half0, from regs) + W3 transpose load (half1) ----
    if (!half) {
        #pragma unroll
        for (int i = 0; i < 4; i++) {
            int j = jg * 4 + i;
            u64 gp = pk2(g2[j], g2[j]);
            u64 bp = pk2(be2[j], be2[j]);
            #pragma unroll
            for (int m = 0; m < 4; m++) {
                int rp = rg * 4 + m;
                u64 t = add2(h2[i][m], negmu[rp]);
                t = mul2(t, srs[rp]);
                t = fma2(t, gp, bp);
                float x, y; upk2(t, x, y);
                sh2tU[j * 17 + rp] = pk2(fmaxf(x, 0.f), fmaxf(y, 0.f));
            }
        }
    } else {
        for (int i = tid - 128; i < H2N * EE; i += 128) {
            int k = i >> 3, e = i & 7;
            W3t[e * 132 + k] = W3[i];
        }
    }
    __syncthreads();

    // ---- layer 3 + logits: thread = (row, expert) ----
    {
        int r = tid >> 3, e = tid & 7;    // r 0..31, e 0..7
        int rp = r >> 1, sel = r & 1;
        float acc = b3[e];
        #pragma unroll 4
        for (int k = 0; k < H2N; k++)
            acc = fmaf(sh2tF[(k * 17 + rp) * 2 + sel], W3t[e * 132 + k], acc);
        lout[(size_t)(rb + r) * EE + e] = acc;
        slog[r * 8 + e] = acc;
    }
    __syncthreads();
    if (tid < MROWS) {
        int r = tid;
        float mx = -1e30f;
        #pragma unroll
        for (int e = 0; e < EE; e++) mx = fmaxf(mx, slog[r * 8 + e]);
        float ex[EE]; float s = 0.f;
        #pragma unroll
        for (int e = 0; e < EE; e++) { ex[e] = __expf(slog[r * 8 + e] - mx); s += ex[e]; }
        float inv = 1.0f / s;
        #pragma unroll
        for (int e = 0; e < EE; e++) wout[(size_t)(rb + r) * EE + e] = ex[e] * inv;
    }
}

extern "C" void kernel_launch(void* const* d_in, const int* in_sizes, int n_in,
                              void* d_out, int out_size)
{
    const float* post = (const float*)d_in[0];
    const float* W1   = (const float*)d_in[1];
    const float* b1   = (const float*)d_in[2];
    const float* g1   = (const float*)d_in[3];
    const float* be1  = (const float*)d_in[4];
    const float* W2   = (const float*)d_in[5];
    const float* b2   = (const float*)d_in[6];
    const float* g2   = (const float*)d_in[7];
    const float* be2  = (const float*)d_in[8];
    const float* W3   = (const float*)d_in[9];
    const float* b3   = (const float*)d_in[10];

    float* out  = (float*)d_out;
    float* wout = out;                         // weights (B, 8)
    float* lout = out + (size_t)BQ * EE;       // logits  (B, 8)
    float* fout = out + (size_t)BQ * EE * 2;   // feats   (B, 59)

    cudaFuncSetAttribute(mlp_kernel, cudaFuncAttributeMaxDynamicSharedMemorySize,
                         MLP_SMEM);

    feat_kernel<<<BQ, 512>>>(post, fout);
    mlp_kernel<<<BQ / MROWS, 256, MLP_SMEM>>>(fout, W1, b1, g1, be1,
                                              W2, b2, g2, be2, W3, b3,
                                              wout, lout);
}

// round 5
// speedup vs baseline: 1.5247x; 1.0257x over previous
#include <cuda_runtime.h>

#define BQ 16384
#define EE 8
#define CC 1000
#define DD 59
#define H1N 256
#define H2N 128
#define EPSF 1e-8f
#define LN_EPSF 1e-5f
#define MROWS 16
#define LN2F 0.69314718055994530942f

typedef unsigned long long u64;

__device__ __forceinline__ float wsum(float v) {
    #pragma unroll
    for (int o = 16; o; o >>= 1) v += __shfl_xor_sync(0xffffffffu, v, o);
    return v;
}

// ---- f32x2 packed helpers (sm_100+) ----
__device__ __forceinline__ u64 pk2(float a, float b) {
    u64 r; asm("mov.b64 %0, {%1, %2};" : "=l"(r) : "f"(a), "f"(b)); return r;
}
__device__ __forceinline__ void upk2(u64 v, float& a, float& b) {
    asm("mov.b64 {%0, %1}, %2;" : "=f"(a), "=f"(b) : "l"(v));
}
__device__ __forceinline__ u64 fma2(u64 a, u64 b, u64 c) {
    u64 d; asm("fma.rn.f32x2 %0, %1, %2, %3;" : "=l"(d) : "l"(a), "l"(b), "l"(c)); return d;
}
__device__ __forceinline__ u64 add2(u64 a, u64 b) {
    u64 d; asm("add.rn.f32x2 %0, %1, %2;" : "=l"(d) : "l"(a), "l"(b)); return d;
}
__device__ __forceinline__ u64 mul2(u64 a, u64 b) {
    u64 d; asm("mul.rn.f32x2 %0, %1, %2;" : "=l"(d) : "l"(a), "l"(b)); return d;
}
__device__ __forceinline__ u64 wsum2(u64 v) {
    #pragma unroll
    for (int o = 16; o; o >>= 1) v = add2(v, __shfl_xor_sync(0xffffffffu, v, o));
    return v;
}

#define CE(a, b) { float _h = fmaxf(a, b); b = fminf(a, b); a = _h; }

__device__ __forceinline__ void ins5(float& a0, float& a1, float& a2, float& a3,
                                     float& a4, float v) {
    CE(a0, v); CE(a1, v); CE(a2, v); CE(a3, v); a4 = fmaxf(a4, v);
}

// ---------------------------------------------------------------------------
// Kernel 1: feature extraction (unchanged from R4). One block per row.
// ---------------------------------------------------------------------------
__global__ __launch_bounds__(512, 3) void feat_kernel(
    const float* __restrict__ post, float* __restrict__ feats_out)
{
    __shared__ __align__(16) float sp[EE * CC];
    __shared__ __align__(16) float smp[CC];
    __shared__ __align__(16) float slmp2[CC];
    __shared__ float redA[16][2];
    __shared__ float wq[16][4];
    __shared__ float wtop[16][5];
    __shared__ float sfeat[DD];

    const int tid  = threadIdx.x;
    const int row  = blockIdx.x;
    const int w    = tid >> 5;
    const int lane = tid & 31;

    {
        const float4* src = reinterpret_cast<const float4*>(post + (size_t)row * (EE * CC));
        float4* dst = reinterpret_cast<float4*>(sp);
        #pragma unroll
        for (int i = 0; i < 4; i++) {
            int idx = tid + i * 512;
            if (idx < (EE * CC) / 4) dst[idx] = src[idx];
        }
    }
    __syncthreads();

    {
        float ment2 = 0.f, mn2 = 0.f;
        if (tid < 500) {
            const u64* spU = reinterpret_cast<const u64*>(sp);
            u64 a = spU[tid];
            #pragma unroll
            for (int e = 1; e < EE; e++) a = add2(a, spU[e * 500 + tid]);
            u64 mp2 = mul2(a, pk2(0.125f, 0.125f));
            float mx, my; upk2(mp2, mx, my);
            float lx = __log2f(mx + EPSF), ly = __log2f(my + EPSF);
            reinterpret_cast<u64*>(smp)[tid]   = mp2;
            reinterpret_cast<u64*>(slmp2)[tid] = pk2(lx, ly);
            ment2 = fmaf(mx, lx, 0.f); ment2 = fmaf(my, ly, ment2);
            mn2   = fmaf(mx, mx, 0.f); mn2   = fmaf(my, my, mn2);
        }
        ment2 = wsum(ment2); mn2 = wsum(mn2);
        if (lane == 0) { redA[w][0] = ment2; redA[w][1] = mn2; }
    }
    __syncthreads();

    {
        const int e = w & 7;
        const int h = w >> 3;
        const float4* p4 = reinterpret_cast<const float4*>(sp + e * CC);
        const float4* m4 = reinterpret_cast<const float4*>(smp);
        const float4* l4 = reinterpret_cast<const float4*>(slmp2);

        float A = 0.f;
        u64 SQ2 = 0ull, DOT2 = 0ull, B2 = 0ull;
        float a0 = 0.f, a1 = 0.f, a2 = 0.f, a3 = 0.f, a4 = 0.f;

        const int base = h * 125 + lane;
        #pragma unroll
        for (int it = 0; it < 4; it++) {
            if (it < 3 || lane < 29) {
                int i = base + it * 32;
                float4 p  = p4[i];
                float4 mm = m4[i];
                float4 lm = l4[i];
                u64 pa = pk2(p.x, p.y), pb = pk2(p.z, p.w);
                SQ2  = fma2(pa, pa, SQ2);              SQ2  = fma2(pb, pb, SQ2);
                DOT2 = fma2(pa, pk2(mm.x, mm.y), DOT2); DOT2 = fma2(pb, pk2(mm.z, mm.w), DOT2);
                B2   = fma2(pa, pk2(lm.x, lm.y), B2);   B2   = fma2(pb, pk2(lm.z, lm.w), B2);
                float lx = __log2f(p.x + EPSF);
                float ly = __log2f(p.y + EPSF);
                float lz = __log2f(p.z + EPSF);
                float lw = __log2f(p.w + EPSF);
                A = fmaf(p.x, lx, A); A = fmaf(p.y, ly, A);
                A = fmaf(p.z, lz, A); A = fmaf(p.w, lw, A);

                float v0 = p.x, v1 = p.y, v2 = p.z, v3 = p.w;
                CE(v0, v1); CE(v2, v3); CE(v0, v2); CE(v1, v3); CE(v1, v2);
                CE(a0, v0); CE(a1, v0); CE(a2, v0); CE(a3, v0); a4 = fmaxf(a4, v0);
                CE(a1, v1); CE(a2, v1); CE(a3, v1); a4 = fmaxf(a4, v1);
                CE(a2, v2); CE(a3, v2); a4 = fmaxf(a4, v2);
                CE(a3, v3); a4 = fmaxf(a4, v3);
            }
        }

        float sqa, sqb, da, db, ba, bb;
        upk2(SQ2, sqa, sqb); upk2(DOT2, da, db); upk2(B2, ba, bb);
        float SQ = sqa + sqb, DOT = da + db, B = ba + bb;

        A = wsum(A); B = wsum(B); SQ = wsum(SQ); DOT = wsum(DOT);

        float top[5];
        int ptr = 0;
        #pragma unroll
        for (int k = 0; k < 5; k++) {
            float v = a0;
            if      (ptr == 1) v = a1;
            else if (ptr == 2) v = a2;
            else if (ptr == 3) v = a3;
            else if (ptr == 4) v = a4;
            else if (ptr >= 5) v = 0.f;
            unsigned uv = __float_as_uint(v);
            unsigned um = __reduce_max_sync(0xffffffffu, uv);
            top[k] = __uint_as_float(um);
            unsigned msk = __ballot_sync(0xffffffffu, uv == um);
            if (lane == (__ffs(msk) - 1)) ptr++;
        }

        if (lane == 0) {
            wq[w][0] = A; wq[w][1] = B; wq[w][2] = SQ; wq[w][3] = DOT;
            wtop[w][0] = top[0]; wtop[w][1] = top[1]; wtop[w][2] = top[2];
            wtop[w][3] = top[3]; wtop[w][4] = top[4];
        }
    }
    __syncthreads();

    if (tid < EE) {
        int e = tid;
        float A   = wq[e][0] + wq[e + 8][0];
        float B   = wq[e][1] + wq[e + 8][1];
        float SQ  = wq[e][2] + wq[e + 8][2];
        float DOT = wq[e][3] + wq[e + 8][3];
        float t0 = wtop[e][0], t1 = wtop[e][1], t2 = wtop[e][2],
              t3 = wtop[e][3], t4 = wtop[e][4];
        ins5(t0, t1, t2, t3, t4, wtop[e + 8][0]);
        ins5(t0, t1, t2, t3, t4, wtop[e + 8][1]);
        ins5(t0, t1, t2, t3, t4, wtop[e + 8][2]);
        ins5(t0, t1, t2, t3, t4, wtop[e + 8][3]);
        ins5(t0, t1, t2, t3, t4, wtop[e + 8][4]);

        float mn2T = 0.f;
        #pragma unroll
        for (int i = 0; i < 16; i++) mn2T += redA[i][1];
        float mn = fmaxf(sqrtf(mn2T), EPSF);
        float pn = fmaxf(sqrtf(SQ), EPSF);
        float tkm = t0 + t1 + t2 + t3 + t4;

        sfeat[e]      = -LN2F * A;
        sfeat[8 + e]  = tkm;
        sfeat[16 + e] = 1.0f - tkm;
        sfeat[24 + e] = t0;
        sfeat[32 + e] = t0 - t1;
        sfeat[40 + e] = DOT / (pn * mn);
        sfeat[48 + e] = LN2F * (A - B);
    }
    __syncthreads();

    if (tid == 0) {
        float ment2T = 0.f, mn2T = 0.f, SQall = 0.f;
        #pragma unroll
        for (int i = 0; i < 16; i++) {
            ment2T += redA[i][0];
            mn2T   += redA[i][1];
            SQall  += wq[i][2];
        }
        sfeat[56] = -LN2F * ment2T;
        sfeat[57] = (SQall - 8.0f * mn2T) * (1.0f / 7000.0f);
        float mm = 0.f;
        #pragma unroll
        for (int e = 0; e < EE; e++) mm += sfeat[24 + e];
        mm *= 0.125f;
        float sv = 0.f;
        #pragma unroll
        for (int e = 0; e < EE; e++) { float d = sfeat[24 + e] - mm; sv = fmaf(d, d, sv); }
        sfeat[58] = sqrtf(sv * (1.0f / 7.0f));
    }
    __syncthreads();

    if (tid < DD) {
        float v = sfeat[tid];
        v = fminf(fmaxf(v, -100.0f), 100.0f);
        feats_out[(size_t)row * DD + tid] = v;
    }
}

// ---------------------------------------------------------------------------
// Kernel 2: MLP v5. 16 rows/block (8 rowpairs), 256 threads, grid 1024,
// 2-neuron x 4-rowpair f32x2 tiles, 28.3KB static smem -> 7 blocks/SM,
// single wave (1036 slots >= 1024 blocks).
// smem layout (bytes):
//   sh1t @0     : u64[256*9] = 18432   [j*9 + rp]
//   sh2t @18432 : u64[128*9] =  9216   [j*9 + rp]   (sft u64[59*8] aliased)
//   negmu @27648: u64[8]
//   srs   @27712: u64[8]
//   slog  @27776: float[16*8] = 512
// ---------------------------------------------------------------------------
__global__ __launch_bounds__(256, 7) void mlp_kernel(
    const float* __restrict__ feats,
    const float* __restrict__ W1, const float* __restrict__ b1,
    const float* __restrict__ g1, const float* __restrict__ be1,
    const float* __restrict__ W2, const float* __restrict__ b2,
    const float* __restrict__ g2, const float* __restrict__ be2,
    const float* __restrict__ W3, const float* __restrict__ b3,
    float* __restrict__ wout, float* __restrict__ lout)
{
    __shared__ __align__(16) char smraw[28288];
    u64*   sh1tU = (u64*)(smraw);
    u64*   sh2tU = (u64*)(smraw + 18432);
    u64*   sftU  = (u64*)(smraw + 18432);
    float* sftF  = (float*)(smraw + 18432);
    u64*   negmu = (u64*)(smraw + 27648);
    u64*   srs   = (u64*)(smraw + 27712);
    float* slog  = (float*)(smraw + 27776);

    const int tid  = threadIdx.x;
    const int rb   = blockIdx.x * MROWS;
    const int w    = tid >> 5;
    const int lane = tid & 31;

    // load feats transposed: sftF[d*16 + r]
    for (int i = tid; i < MROWS * DD; i += 256) {
        int r = i / DD, d = i - r * DD;
        sftF[d * 16 + r] = feats[(size_t)rb * DD + i];
    }
    __syncthreads();

    // ---- layer 1: 2 neurons x 4 rowpairs per thread ----
    const int ng = tid >> 1;          // 0..127 -> neurons 2ng, 2ng+1
    const int rg = tid & 1;           // rowpairs rg*4 .. rg*4+3
    {
        u64 acc[2][4];
        #pragma unroll
        for (int i = 0; i < 2; i++)
            #pragma unroll
            for (int m = 0; m < 4; m++) acc[i][m] = 0ull;

        const float2* w1p = reinterpret_cast<const float2*>(W1 + ng * 2);
        const u64* fp = sftU + rg * 4;
        for (int d = 0; d < DD; d++) {
            float2 wv = w1p[d * (H1N / 2)];
            u64 w0 = pk2(wv.x, wv.x), w1v = pk2(wv.y, wv.y);
            u64 f0 = fp[d * 8 + 0], f1 = fp[d * 8 + 1];
            u64 f2 = fp[d * 8 + 2], f3 = fp[d * 8 + 3];
            acc[0][0] = fma2(f0, w0, acc[0][0]); acc[0][1] = fma2(f1, w0, acc[0][1]);
            acc[0][2] = fma2(f2, w0, acc[0][2]); acc[0][3] = fma2(f3, w0, acc[0][3]);
            acc[1][0] = fma2(f0, w1v, acc[1][0]); acc[1][1] = fma2(f1, w1v, acc[1][1]);
            acc[1][2] = fma2(f2, w1v, acc[1][2]); acc[1][3] = fma2(f3, w1v, acc[1][3]);
        }
        float2 bb = *reinterpret_cast<const float2*>(b1 + ng * 2);
        #pragma unroll
        for (int i = 0; i < 2; i++) {
            float b = i ? bb.y : bb.x;
            u64 bp = pk2(b, b);
            #pragma unroll
            for (int m = 0; m < 4; m++)
                sh1tU[(ng * 2 + i) * 9 + rg * 4 + m] = add2(acc[i][m], bp);
        }
    }
    __syncthreads();

    // ---- LN1 stats: warp w handles rowpair w ----
    {
        u64 s = 0ull, q = 0ull;
        #pragma unroll
        for (int m = 0; m < 8; m++) {
            u64 v = sh1tU[(lane + 32 * m) * 9 + w];
            s = add2(s, v);
            q = fma2(v, v, q);
        }
        s = wsum2(s); q = wsum2(q);
        if (lane == 0) {
            float sa, sb, qa, qb;
            upk2(s, sa, sb); upk2(q, qa, qb);
            float mua = sa * (1.0f / H1N), mub = sb * (1.0f / H1N);
            float rsa = rsqrtf(qa * (1.0f / H1N) - mua * mua + LN_EPSF);
            float rsb = rsqrtf(qb * (1.0f / H1N) - mub * mub + LN_EPSF);
            negmu[w] = pk2(-mua, -mub);
            srs[w]   = pk2(rsa, rsb);
        }
    }
    __syncthreads();

    // ---- LN1 apply + relu ----
    {
        float2 gg = *reinterpret_cast<const float2*>(g1 + ng * 2);
        float2 be = *reinterpret_cast<const float2*>(be1 + ng * 2);
        #pragma unroll
        for (int i = 0; i < 2; i++) {
            float g = i ? gg.y : gg.x;
            float b = i ? be.y : be.x;
            u64 gp = pk2(g, g), bp = pk2(b, b);
            int j = ng * 2 + i;
            #pragma unroll
            for (int m = 0; m < 4; m++) {
                int rp = rg * 4 + m;
                u64 t = add2(sh1tU[j * 9 + rp], negmu[rp]);
                t = mul2(t, srs[rp]);
                t = fma2(t, gp, bp);
                float x, y; upk2(t, x, y);
                sh1tU[j * 9 + rp] = pk2(fmaxf(x, 0.f), fmaxf(y, 0.f));
            }
        }
    }
    __syncthreads();

    // ---- layer 2: K=256 split in halves, 2 neurons x 4 rowpairs ----
    const int half = tid >> 7;
    const int t2   = tid & 127;
    const int jg   = t2 >> 1;         // 0..63 -> neurons 2jg, 2jg+1
    const int rg2  = t2 & 1;
    {
        u64 acc[2][4];
        #pragma unroll
        for (int i = 0; i < 2; i++)
            #pragma unroll
            for (int m = 0; m < 4; m++) acc[i][m] = 0ull;

        const int k0 = half * 128;
        const float2* w2p = reinterpret_cast<const float2*>(W2 + jg * 2);
        const u64* hp = sh1tU + rg2 * 4;
        for (int kk = 0; kk < 128; kk++) {
            int k = k0 + kk;
            float2 wv = w2p[k * (H2N / 2)];
            u64 w0 = pk2(wv.x, wv.x), w1v = pk2(wv.y, wv.y);
            u64 f0 = hp[k * 9 + 0], f1 = hp[k * 9 + 1];
            u64 f2 = hp[k * 9 + 2], f3 = hp[k * 9 + 3];
            acc[0][0] = fma2(f0, w0, acc[0][0]); acc[0][1] = fma2(f1, w0, acc[0][1]);
            acc[0][2] = fma2(f2, w0, acc[0][2]); acc[0][3] = fma2(f3, w0, acc[0][3]);
            acc[1][0] = fma2(f0, w1v, acc[1][0]); acc[1][1] = fma2(f1, w1v, acc[1][1]);
            acc[1][2] = fma2(f2, w1v, acc[1][2]); acc[1][3] = fma2(f3, w1v, acc[1][3]);
        }
        if (half) {
            #pragma unroll
            for (int i = 0; i < 2; i++)
                #pragma unroll
                for (int m = 0; m < 4; m++)
                    sh2tU[(jg * 2 + i) * 9 + rg2 * 4 + m] = acc[i][m];
        }
        __syncthreads();
        if (!half) {
            float2 bb = *reinterpret_cast<const float2*>(b2 + jg * 2);
            #pragma unroll
            for (int i = 0; i < 2; i++) {
                float b = i ? bb.y : bb.x;
                u64 bp = pk2(b, b);
                int j = jg * 2 + i;
                #pragma unroll
                for (int m = 0; m < 4; m++) {
                    int rp = rg2 * 4 + m;
                    sh2tU[j * 9 + rp] = add2(add2(acc[i][m], sh2tU[j * 9 + rp]), bp);
                }
            }
        }
    }
    __syncthreads();

    // ---- LN2 stats: warp w handles rowpair w ----
    {
        u64 s = 0ull, q = 0ull;
        #pragma unroll
        for (int m = 0; m < 4; m++) {
            u64 v = sh2tU[(lane + 32 * m) * 9 + w];
            s = add2(s, v);
            q = fma2(v, v, q);
        }
        s = wsum2(s); q = wsum2(q);
        if (lane == 0) {
            float sa, sb, qa, qb;
            upk2(s, sa, sb); upk2(q, qa, qb);
            float mua = sa * (1.0f / H2N), mub = sb * (1.0f / H2N);
            float rsa = rsqrtf(qa * (1.0f / H2N) - mua * mua + LN_EPSF);
            float rsb = rsqrtf(qb * (1.0f / H2N) - mub * mub + LN_EPSF);
            negmu[w] = pk2(-mua, -mub);
            srs[w]   = pk2(rsa, rsb);
        }
    }
    __syncthreads();

    // ---- LN2 apply + relu (half 0 only: 128 threads cover 128n x 8rp) ----
    if (!half) {
        float2 gg = *reinterpret_cast<const float2*>(g2 + jg * 2);
        float2 be = *reinterpret_cast<const float2*>(be2 + jg * 2);
        #pragma unroll
        for (int i = 0; i < 2; i++) {
            float g = i ? gg.y : gg.x;
            float b = i ? be.y : be.x;
            u64 gp = pk2(g, g), bp = pk2(b, b);
            int j = jg * 2 + i;
            #pragma unroll
            for (int m = 0; m < 4; m++) {
                int rp = rg2 * 4 + m;
                u64 t = add2(sh2tU[j * 9 + rp], negmu[rp]);
                t = mul2(t, srs[rp]);
                t = fma2(t, gp, bp);
                float x, y; upk2(t, x, y);
                sh2tU[j * 9 + rp] = pk2(fmaxf(x, 0.f), fmaxf(y, 0.f));
            }
        }
    }
    __syncthreads();

    // ---- layer 3: thread (rp, e), 64 threads, f32x2 over row pairs ----
    if (tid < 64) {
        int rp = tid >> 3, e = tid & 7;
        float b = b3[e];
        u64 acc = pk2(b, b);
        #pragma unroll 4
        for (int k = 0; k < H2N; k++) {
            float w3 = W3[k * EE + e];
            acc = fma2(sh2tU[k * 9 + rp], pk2(w3, w3), acc);
        }
        float la, lb; upk2(acc, la, lb);
        lout[(size_t)(rb + 2 * rp) * EE + e]     = la;
        lout[(size_t)(rb + 2 * rp + 1) * EE + e] = lb;
        slog[(2 * rp) * 8 + e]     = la;
        slog[(2 * rp + 1) * 8 + e] = lb;
    }
    __syncthreads();

    // ---- softmax: thread per row ----
    if (tid < MROWS) {
        int r = tid;
        float mx = -1e30f;
        #pragma unroll
        for (int e = 0; e < EE; e++) mx = fmaxf(mx, slog[r * 8 + e]);
        float ex[EE]; float s = 0.f;
        #pragma unroll
        for (int e = 0; e < EE; e++) { ex[e] = __expf(slog[r * 8 + e] - mx); s += ex[e]; }
        float inv = 1.0f / s;
        #pragma unroll
        for (int e = 0; e < EE; e++) wout[(size_t)(rb + r) * EE + e] = ex[e] * inv;
    }
}

extern "C" void kernel_launch(void* const* d_in, const int* in_sizes, int n_in,
                              void* d_out, int out_size)
{
    const float* post = (const float*)d_in[0];
    const float* W1   = (const float*)d_in[1];
    const float* b1   = (const float*)d_in[2];
    const float* g1   = (const float*)d_in[3];
    const float* be1  = (const float*)d_in[4];
    const float* W2   = (const float*)d_in[5];
    const float* b2   = (const float*)d_in[6];
    const float* g2   = (const float*)d_in[7];
    const float* be2  = (const float*)d_in[8];
    const float* W3   = (const float*)d_in[9];
    const float* b3   = (const float*)d_in[10];

    float* out  = (float*)d_out;
    float* wout = out;                         // weights (B, 8)
    float* lout = out + (size_t)BQ * EE;       // logits  (B, 8)
    float* fout = out + (size_t)BQ * EE * 2;   // feats   (B, 59)

    feat_kernel<<<BQ, 512>>>(post, fout);
    mlp_kernel<<<BQ / MROWS, 256>>>(fout, W1, b1, g1, be1,
                                    W2, b2, g2, be2, W3, b3,
                                    wout, lout);
}